// round 4
// baseline (speedup 1.0000x reference)
#include <cuda_runtime.h>
#include <cuda_bf16.h>

// Batched Bloch RK4. RHS is affine per batch element:
//   u' = -g u ;  [v w]' = [[-g,-Om],[Om,-2g]][v w] + [0,-2g]
// RK4 with step h on y'=Ay+b is EXACTLY y+ = M y + c with
//   M = I + Bm + Bm^2/2 + Bm^3/6 + Bm^4/24   (Bm = h*A)
//   c = (hI + h^2 A/2 + h^3 A^2/6 + h^4 A^3/24) b
// 4 batch elements/thread -> per-step output is 3x STG.128.
// Propagators in a 2-slot LRU keyed on the fp32 dt value (dt of
// arange(T)*0.01f alternates between adjacent representables).
//
// Time-split: kernel1 runs the recurrence storing only NCHUNK-1 checkpoint
// states (bit-exact same op sequence); kernel2 runs NCHUNK time-chunks in
// parallel for 16x occupancy on the store-heavy pass.

#ifndef TMAX
#define TMAX 2048
#endif

#define NCHUNK 16
#define MAXB   65536
// checkpoint c (1..NCHUNK-1) = full state after c*L steps
__device__ float g_ckpt[(NCHUNK - 1) * MAXB * 3];

__device__ __forceinline__ void make_prop(
    float h, const float Om[4], const float g[4],
    float pu[4], float m00[4], float m01[4], float m10[4], float m11[4],
    float c0[4], float c1[4])
{
    const float i6 = 1.f / 6.f, i24 = 1.f / 24.f;
#pragma unroll
    for (int j = 0; j < 4; ++j) {
        float b00 = -g[j] * h, b01 = -Om[j] * h, b10 = Om[j] * h, b11 = -2.f * g[j] * h;
        float s00 = b00 * b00 + b01 * b10;
        float s01 = b00 * b01 + b01 * b11;
        float s10 = b10 * b00 + b11 * b10;
        float s11 = b10 * b01 + b11 * b11;
        float t00 = s00 * b00 + s01 * b10;
        float t01 = s00 * b01 + s01 * b11;
        float t10 = s10 * b00 + s11 * b10;
        float t11 = s10 * b01 + s11 * b11;
        float q00 = s00 * s00 + s01 * s10;
        float q01 = s00 * s01 + s01 * s11;
        float q10 = s10 * s00 + s11 * s10;
        float q11 = s10 * s01 + s11 * s11;
        m00[j] = 1.f + b00 + 0.5f * s00 + i6 * t00 + i24 * q00;
        m01[j] =       b01 + 0.5f * s01 + i6 * t01 + i24 * q01;
        m10[j] =       b10 + 0.5f * s10 + i6 * t10 + i24 * q10;
        m11[j] = 1.f + b11 + 0.5f * s11 + i6 * t11 + i24 * q11;
        float p01 = h * (0.5f * b01 + i6 * s01 + i24 * t01);
        float p11 = h * (1.f + 0.5f * b11 + i6 * s11 + i24 * t11);
        float nb = -2.f * g[j];
        c0[j] = p01 * nb;
        c1[j] = p11 * nb;
        float be = -g[j] * h;
        pu[j] = 1.f + be * (1.f + be * (0.5f + be * (i6 + be * i24)));
    }
}

#define APPLY(pu, m00, m01, m10, m11, c0, c1)                               \
    _Pragma("unroll")                                                       \
    for (int j = 0; j < 4; ++j) {                                           \
        u[j] = pu[j] * u[j];                                                \
        float vn = fmaf(m00[j], v[j], fmaf(m01[j], w[j], c0[j]));           \
        float wn = fmaf(m10[j], v[j], fmaf(m11[j], w[j], c1[j]));           \
        v[j] = vn; w[j] = wn;                                               \
    }

// One RK4 step via the 2-slot LRU cache. Uses surrounding locals.
#define STEP_WITH_CACHE()                                                   \
    do {                                                                    \
        if (h == hA) {                                                      \
            APPLY(Apu, Am00, Am01, Am10, Am11, Ac0, Ac1);                   \
            lastA = true;                                                   \
        } else if (h == hB) {                                               \
            APPLY(Bpu, Bm00, Bm01, Bm10, Bm11, Bc0, Bc1);                   \
            lastA = false;                                                  \
        } else if (!lastA) {                                                \
            make_prop(h, Om, g, Apu, Am00, Am01, Am10, Am11, Ac0, Ac1);     \
            hA = h;                                                         \
            APPLY(Apu, Am00, Am01, Am10, Am11, Ac0, Ac1);                   \
            lastA = true;                                                   \
        } else {                                                            \
            make_prop(h, Om, g, Bpu, Bm00, Bm01, Bm10, Bm11, Bc0, Bc1);     \
            hB = h;                                                         \
            APPLY(Bpu, Bm00, Bm01, Bm10, Bm11, Bc0, Bc1);                   \
            lastA = false;                                                  \
        }                                                                   \
    } while (0)

#define DECL_CACHE()                                                        \
    float Apu[4], Am00[4], Am01[4], Am10[4], Am11[4], Ac0[4], Ac1[4];       \
    float Bpu[4], Bm00[4], Bm01[4], Bm10[4], Bm11[4], Bc0[4], Bc1[4];       \
    float hA = __int_as_float(0x7fc00000);                                  \
    float hB = __int_as_float(0x7fc00000);                                  \
    bool lastA = false;

__device__ __forceinline__ void load_state4(
    const float* __restrict__ src, long long base,
    float u[4], float v[4], float w[4])
{
    const float4* s4 = (const float4*)(src + base * 3);
    float4 a0 = s4[0], a1 = s4[1], a2 = s4[2];
    u[0] = a0.x; v[0] = a0.y; w[0] = a0.z;
    u[1] = a0.w; v[1] = a1.x; w[1] = a1.y;
    u[2] = a1.z; v[2] = a1.w; w[2] = a2.x;
    u[3] = a2.y; v[3] = a2.z; w[3] = a2.w;
}

__device__ __forceinline__ void load_params4(
    const float* __restrict__ params, long long base, float Om[4], float g[4])
{
    const float4* p4 = (const float4*)(params + base * 3);
    float4 q0 = p4[0], q1 = p4[1], q2 = p4[2];
    Om[0] = q0.x; g[0] = q0.z;
    Om[1] = q0.w; g[1] = q1.y;
    Om[2] = q1.z; g[2] = q2.x;
    Om[3] = q2.y; g[3] = q2.w;
}

__device__ __forceinline__ void store_state4_cs(
    float4* o, const float u[4], const float v[4], const float w[4])
{
    __stcs(o + 0, make_float4(u[0], v[0], w[0], u[1]));
    __stcs(o + 1, make_float4(v[1], w[1], u[2], v[2]));
    __stcs(o + 2, make_float4(w[2], u[3], v[3], w[3]));
}

// ---------------- Kernel 1: compute checkpoint states only ----------------
__global__ __launch_bounds__(256) void bloch_ckpt_kernel(
    const float* __restrict__ y0,
    const float* __restrict__ ts,
    const float* __restrict__ params,
    int B, int T, int L)
{
    __shared__ float s_ts[TMAX];
    int tcap = (T < TMAX) ? T : TMAX;
    for (int i = threadIdx.x; i < tcap; i += blockDim.x) s_ts[i] = ts[i];
    __syncthreads();

    int tid = blockIdx.x * blockDim.x + threadIdx.x;
    long long base = 4LL * tid;
    if (base >= B) return;

    float u[4], v[4], w[4], Om[4], g[4];
    load_state4(y0, base, u, v, w);
    load_params4(params, base, Om, g);

    DECL_CACHE();
    float ts_prev = (tcap > 0) ? s_ts[0] : 0.f;

    int s_end = (NCHUNK - 1) * L;
    if (s_end > T - 1) s_end = T - 1;

    int next_c = 1;
    for (int s = 1; s <= s_end; ++s) {
        float ts_cur = (s < TMAX) ? s_ts[s] : __ldg(ts + s);
        float h = ts_cur - ts_prev;
        ts_prev = ts_cur;
        STEP_WITH_CACHE();
        if (s == next_c * L) {
            float4* o = (float4*)(g_ckpt + (long long)(next_c - 1) * B * 3 + base * 3);
            // L2-resident: kernel 2 reads these right back
            __stcg(o + 0, make_float4(u[0], v[0], w[0], u[1]));
            __stcg(o + 1, make_float4(v[1], w[1], u[2], v[2]));
            __stcg(o + 2, make_float4(w[2], u[3], v[3], w[3]));
            ++next_c;
        }
    }
}

// ---------------- Kernel 2: parallel-in-time output pass ----------------
__global__ __launch_bounds__(128) void bloch_chunk_kernel(
    const float* __restrict__ y0,
    const float* __restrict__ ts,
    const float* __restrict__ params,
    float* __restrict__ out,
    int B, int T, int L)
{
    __shared__ float s_ts[TMAX];
    int tcap = (T < TMAX) ? T : TMAX;
    for (int i = threadIdx.x; i < tcap; i += blockDim.x) s_ts[i] = ts[i];
    __syncthreads();

    int c = blockIdx.y;                   // time chunk
    int tid = blockIdx.x * blockDim.x + threadIdx.x;
    long long base = 4LL * tid;
    if (base >= B) return;

    int sc = 1 + c * L;                   // first step index of this chunk
    if (sc >= T) return;
    int se = sc + L;                      // one past last
    if (se > T) se = T;

    float u[4], v[4], w[4], Om[4], g[4];
    if (c == 0) {
        load_state4(y0, base, u, v, w);
    } else {
        load_state4(g_ckpt + (long long)(c - 1) * B * 3, base, u, v, w);
    }
    load_params4(params, base, Om, g);

    const long long strideF4 = (3LL * B) / 4;
    float4* o = (float4*)(out + base * 3) + (long long)(sc - 1) * strideF4;

    if (c == 0) {
        // t = 0 row is y0 itself
        store_state4_cs(o, u, v, w);
    }

    DECL_CACHE();
    float ts_prev = ((sc - 1) < TMAX) ? s_ts[sc - 1] : __ldg(ts + sc - 1);

    for (int s = sc; s < se; ++s) {
        float ts_cur = (s < TMAX) ? s_ts[s] : __ldg(ts + s);
        float h = ts_cur - ts_prev;
        ts_prev = ts_cur;
        STEP_WITH_CACHE();
        o += strideF4;
        store_state4_cs(o, u, v, w);
    }
}

// ---------------- scalar fallback (B % 4 != 0 or B too big) ----------------
__global__ __launch_bounds__(256) void bloch_rk4_scalar(
    const float* __restrict__ y0,
    const float* __restrict__ ts,
    const float* __restrict__ params,
    float* __restrict__ out,
    int B, int T)
{
    __shared__ float s_ts[TMAX];
    int tcap = (T < TMAX) ? T : TMAX;
    for (int i = threadIdx.x; i < tcap; i += blockDim.x) s_ts[i] = ts[i];
    __syncthreads();

    int b = blockIdx.x * blockDim.x + threadIdx.x;
    if (b >= B) return;

    float uu = y0[3 * b + 0], vv = y0[3 * b + 1], ww = y0[3 * b + 2];
    float Omv = params[3 * b + 0];
    float gv  = params[3 * b + 2];

    const long long B3 = 3LL * B;
    float* o = out + 3LL * b;
    o[0] = uu; o[1] = vv; o[2] = ww;

    float Om[4] = {Omv, Omv, Omv, Omv}, g[4] = {gv, gv, gv, gv};
    float u[4] = {uu, 0, 0, 0}, v[4] = {vv, 0, 0, 0}, w[4] = {ww, 0, 0, 0};
    DECL_CACHE();
    float ts_prev = (tcap > 0) ? s_ts[0] : 0.f;

    for (int t = 1; t < T; ++t) {
        float ts_cur = (t < TMAX) ? s_ts[t] : __ldg(ts + t);
        float h = ts_cur - ts_prev;
        ts_prev = ts_cur;
        STEP_WITH_CACHE();
        o += B3;
        o[0] = u[0]; o[1] = v[0]; o[2] = w[0];
    }
}

extern "C" void kernel_launch(void* const* d_in, const int* in_sizes, int n_in,
                              void* d_out, int out_size) {
    const float* y0     = (const float*)d_in[0];   // (B,3)
    const float* ts     = (const float*)d_in[1];   // (T,)
    const float* params = (const float*)d_in[2];   // (B,3)
    float* out = (float*)d_out;                    // (T,B,3)

    int B = in_sizes[0] / 3;
    int T = in_sizes[1];

    if ((B & 3) == 0 && B <= MAXB && T >= 2) {
        int nthreads = B / 4;
        int L = (T - 1 + NCHUNK - 1) / NCHUNK;     // steps per chunk

        int tpb1 = 256;
        int bx1 = (nthreads + tpb1 - 1) / tpb1;
        bloch_ckpt_kernel<<<bx1, tpb1>>>(y0, ts, params, B, T, L);

        int tpb2 = 128;
        int bx2 = (nthreads + tpb2 - 1) / tpb2;
        dim3 grid(bx2, NCHUNK);
        bloch_chunk_kernel<<<grid, tpb2>>>(y0, ts, params, out, B, T, L);
    } else {
        int tpb = 256;
        int blocks = (B + tpb - 1) / tpb;
        bloch_rk4_scalar<<<blocks, tpb>>>(y0, ts, params, out, B, T);
    }
}

// round 5
// speedup vs baseline: 1.6050x; 1.6050x over previous
#include <cuda_runtime.h>
#include <cuda_bf16.h>

// Batched Bloch RK4. RHS is affine per batch element:
//   u' = -g u ;  [v w]' = [[-g,-Om],[Om,-2g]][v w] + [0,-2g]
// RK4 with step h on y'=Ay+b is EXACTLY y+ = M y + c  (degree-4 Taylor).
//
// Two-phase time-split:
//   kernel1: sequential recurrence, stores NCHUNK-1 checkpoint states only.
//   kernel2: NCHUNK time-chunks in parallel; each THREAD owns one output
//            float4 per step (spans exactly 2 batch elements, which it
//            simulates redundantly) -> lane-contiguous STG.128, no replays.

#ifndef TMAX
#define TMAX 2048
#endif

#define NCHUNK 16
#define MAXB   65536
__device__ float g_ckpt[(NCHUNK - 1) * MAXB * 3];

template <int N> struct Prop {
    float pu[N], m00[N], m01[N], m10[N], m11[N], c0[N], c1[N];
};

template <int N>
__device__ __forceinline__ void make_prop(float h, const float* Om, const float* g,
                                          Prop<N>& P)
{
    const float i6 = 1.f / 6.f, i24 = 1.f / 24.f;
#pragma unroll
    for (int j = 0; j < N; ++j) {
        float b00 = -g[j] * h, b01 = -Om[j] * h, b10 = Om[j] * h, b11 = -2.f * g[j] * h;
        float s00 = b00 * b00 + b01 * b10;
        float s01 = b00 * b01 + b01 * b11;
        float s10 = b10 * b00 + b11 * b10;
        float s11 = b10 * b01 + b11 * b11;
        float t00 = s00 * b00 + s01 * b10;
        float t01 = s00 * b01 + s01 * b11;
        float t10 = s10 * b00 + s11 * b10;
        float t11 = s10 * b01 + s11 * b11;
        float q00 = s00 * s00 + s01 * s10;
        float q01 = s00 * s01 + s01 * s11;
        float q10 = s10 * s00 + s11 * s10;
        float q11 = s10 * s01 + s11 * s11;
        P.m00[j] = 1.f + b00 + 0.5f * s00 + i6 * t00 + i24 * q00;
        P.m01[j] =       b01 + 0.5f * s01 + i6 * t01 + i24 * q01;
        P.m10[j] =       b10 + 0.5f * s10 + i6 * t10 + i24 * q10;
        P.m11[j] = 1.f + b11 + 0.5f * s11 + i6 * t11 + i24 * q11;
        float p01 = h * (0.5f * b01 + i6 * s01 + i24 * t01);
        float p11 = h * (1.f + 0.5f * b11 + i6 * s11 + i24 * t11);
        float nb = -2.f * g[j];
        P.c0[j] = p01 * nb;
        P.c1[j] = p11 * nb;
        float be = -g[j] * h;
        P.pu[j] = 1.f + be * (1.f + be * (0.5f + be * (i6 + be * i24)));
    }
}

template <int N>
__device__ __forceinline__ void apply_prop(const Prop<N>& P, float* u, float* v, float* w)
{
#pragma unroll
    for (int j = 0; j < N; ++j) {
        u[j] = P.pu[j] * u[j];
        float vn = fmaf(P.m00[j], v[j], fmaf(P.m01[j], w[j], P.c0[j]));
        float wn = fmaf(P.m10[j], v[j], fmaf(P.m11[j], w[j], P.c1[j]));
        v[j] = vn; w[j] = wn;
    }
}

// 2-slot LRU propagator cache keyed on the fp32 dt value (dt of a float
// arange*0.01 takes 2 values per binade + rare transients at crossings).
template <int N> struct PropCache {
    Prop<N> P0, P1;
    float h0, h1;
    bool last0;
    __device__ __forceinline__ void init() {
        h0 = __int_as_float(0x7fc00000);
        h1 = __int_as_float(0x7fc00000);
        last0 = false;
    }
    __device__ __forceinline__ void step(float h, const float* Om, const float* g,
                                         float* u, float* v, float* w) {
        if (h == h0)       { apply_prop(P0, u, v, w); last0 = true;  }
        else if (h == h1)  { apply_prop(P1, u, v, w); last0 = false; }
        else if (!last0)   { make_prop(h, Om, g, P0); h0 = h;
                             apply_prop(P0, u, v, w); last0 = true;  }
        else               { make_prop(h, Om, g, P1); h1 = h;
                             apply_prop(P1, u, v, w); last0 = false; }
    }
};

// Build h[s] = ts[s]-ts[s-1] in shared memory (s in [1,T)).
__device__ __forceinline__ void build_h(const float* __restrict__ ts, float* s_h, int T)
{
    for (int i = threadIdx.x + 1; i < T; i += blockDim.x)
        s_h[i] = ts[i] - ts[i - 1];
    __syncthreads();
}

// ---------------- Kernel 1: checkpoint states only (4 elems/thread) --------
__global__ __launch_bounds__(128) void bloch_ckpt_kernel(
    const float* __restrict__ y0,
    const float* __restrict__ ts,
    const float* __restrict__ params,
    int B, int T, int L)
{
    __shared__ float s_h[TMAX];
    build_h(ts, s_h, T);

    int tid = blockIdx.x * blockDim.x + threadIdx.x;
    long long base = 4LL * tid;
    if (base >= B) return;

    float u[4], v[4], w[4], Om[4], g[4];
    {
        const float4* s4 = (const float4*)(y0 + base * 3);
        float4 a0 = s4[0], a1 = s4[1], a2 = s4[2];
        u[0] = a0.x; v[0] = a0.y; w[0] = a0.z;
        u[1] = a0.w; v[1] = a1.x; w[1] = a1.y;
        u[2] = a1.z; v[2] = a1.w; w[2] = a2.x;
        u[3] = a2.y; v[3] = a2.z; w[3] = a2.w;
        const float4* p4 = (const float4*)(params + base * 3);
        float4 q0 = p4[0], q1 = p4[1], q2 = p4[2];
        Om[0] = q0.x; g[0] = q0.z;
        Om[1] = q0.w; g[1] = q1.y;
        Om[2] = q1.z; g[2] = q2.x;
        Om[3] = q2.y; g[3] = q2.w;
    }

    PropCache<4> C;
    C.init();

    int s_end = (NCHUNK - 1) * L;
    if (s_end > T - 1) s_end = T - 1;

    int next_c = 1;
    for (int s = 1; s <= s_end; ++s) {
        C.step(s_h[s], Om, g, u, v, w);
        if (s == next_c * L) {
            float4* o = (float4*)(g_ckpt + (long long)(next_c - 1) * B * 3 + base * 3);
            __stcg(o + 0, make_float4(u[0], v[0], w[0], u[1]));
            __stcg(o + 1, make_float4(v[1], w[1], u[2], v[2]));
            __stcg(o + 2, make_float4(w[2], u[3], v[3], w[3]));
            ++next_c;
        }
    }
}

// ------- Kernel 2: output pass, one float4 per thread per step -------------
// float4 f of a row covers floats [4f,4f+4) = components of elements e,e+1
// with e = (4f)/3, off = 4f-3e. Thread simulates both elements.
__global__ __launch_bounds__(128) void bloch_out_kernel(
    const float* __restrict__ y0,
    const float* __restrict__ ts,
    const float* __restrict__ params,
    float* __restrict__ out,
    int B, int T, int L)
{
    __shared__ float s_h[TMAX];
    build_h(ts, s_h, T);

    int c = blockIdx.y;
    int f = blockIdx.x * blockDim.x + threadIdx.x;
    int F = (3 * B) / 4;                 // float4s per timestep row
    if (f >= F) return;

    int sc = 1 + c * L;                  // first step of this chunk
    if (sc >= T) return;
    int se = sc + L;
    if (se > T) se = T;

    int e   = (4 * f) / 3;
    int off = 4 * f - 3 * e;

    const float* src = (c == 0) ? y0 : (g_ckpt + (long long)(c - 1) * B * 3);
    float u[2], v[2], w[2], Om[2], g[2];
    u[0] = src[3 * e + 0]; v[0] = src[3 * e + 1]; w[0] = src[3 * e + 2];
    u[1] = src[3 * e + 3]; v[1] = src[3 * e + 4]; w[1] = src[3 * e + 5];
    Om[0] = params[3 * e + 0]; g[0] = params[3 * e + 2];
    Om[1] = params[3 * e + 3]; g[1] = params[3 * e + 5];

    float4* orow = (float4*)out + (long long)(sc - 1) * F + f;

    if (c == 0) {
        float x0 = (off == 0) ? u[0] : ((off == 1) ? v[0] : w[0]);
        float x1 = (off == 0) ? v[0] : ((off == 1) ? w[0] : u[1]);
        float x2 = (off == 0) ? w[0] : ((off == 1) ? u[1] : v[1]);
        float x3 = (off == 0) ? u[1] : ((off == 1) ? v[1] : w[1]);
        __stcs(orow, make_float4(x0, x1, x2, x3));
    }

    PropCache<2> C;
    C.init();

    for (int s = sc; s < se; ++s) {
        C.step(s_h[s], Om, g, u, v, w);
        orow += F;
        float x0 = (off == 0) ? u[0] : ((off == 1) ? v[0] : w[0]);
        float x1 = (off == 0) ? v[0] : ((off == 1) ? w[0] : u[1]);
        float x2 = (off == 0) ? w[0] : ((off == 1) ? u[1] : v[1]);
        float x3 = (off == 0) ? u[1] : ((off == 1) ? v[1] : w[1]);
        __stcs(orow, make_float4(x0, x1, x2, x3));
    }
}

// ---------------- scalar fallback (any B, any T) ---------------------------
__global__ __launch_bounds__(256) void bloch_rk4_scalar(
    const float* __restrict__ y0,
    const float* __restrict__ ts,
    const float* __restrict__ params,
    float* __restrict__ out,
    int B, int T)
{
    int b = blockIdx.x * blockDim.x + threadIdx.x;
    if (b >= B) return;

    float u[1] = {y0[3 * b + 0]}, v[1] = {y0[3 * b + 1]}, w[1] = {y0[3 * b + 2]};
    float Om[1] = {params[3 * b + 0]}, g[1] = {params[3 * b + 2]};

    const long long B3 = 3LL * B;
    float* o = out + 3LL * b;
    o[0] = u[0]; o[1] = v[0]; o[2] = w[0];

    PropCache<1> C;
    C.init();
    float ts_prev = ts[0];

    for (int t = 1; t < T; ++t) {
        float ts_cur = __ldg(ts + t);
        float h = ts_cur - ts_prev;
        ts_prev = ts_cur;
        C.step(h, Om, g, u, v, w);
        o += B3;
        o[0] = u[0]; o[1] = v[0]; o[2] = w[0];
    }
}

extern "C" void kernel_launch(void* const* d_in, const int* in_sizes, int n_in,
                              void* d_out, int out_size) {
    const float* y0     = (const float*)d_in[0];   // (B,3)
    const float* ts     = (const float*)d_in[1];   // (T,)
    const float* params = (const float*)d_in[2];   // (B,3)
    float* out = (float*)d_out;                    // (T,B,3)

    int B = in_sizes[0] / 3;
    int T = in_sizes[1];

    if ((B & 3) == 0 && B <= MAXB && T >= 2 && T <= TMAX) {
        int L = (T - 1 + NCHUNK - 1) / NCHUNK;     // steps per chunk

        int n1 = B / 4;
        int tpb1 = 128;
        bloch_ckpt_kernel<<<(n1 + tpb1 - 1) / tpb1, tpb1>>>(y0, ts, params, B, T, L);

        int F = (3 * B) / 4;
        int tpb2 = 128;
        dim3 grid2((F + tpb2 - 1) / tpb2, NCHUNK);
        bloch_out_kernel<<<grid2, tpb2>>>(y0, ts, params, out, B, T, L);
    } else {
        int tpb = 256;
        bloch_rk4_scalar<<<(B + tpb - 1) / tpb, tpb>>>(y0, ts, params, out, B, T);
    }
}

// round 6
// speedup vs baseline: 1.6653x; 1.0376x over previous
#include <cuda_runtime.h>
#include <cuda_bf16.h>

// Batched Bloch RK4. RHS is affine per batch element:
//   u' = -g u ;  [v w]' = [[-g,-Om],[Om,-2g]][v w] + [0,-2g]
// RK4 with step h on y'=Ay+b is EXACTLY y+ = M y + c (degree-4 Taylor).
//
// Two-phase time-split:
//   kernel1: sequential recurrence, 2 elems/thread (latency-optimized),
//            stores NCHUNK-1 checkpoint states only.
//   kernel2: NCHUNK time-chunks in parallel; each THREAD owns one output
//            float4 per step (spans 2 batch elements, simulated redundantly)
//            -> lane-contiguous STG.128. Fixed-trip unrolled fast path.

#ifndef TMAX
#define TMAX 2048
#endif

#define NCHUNK 16
#define MAXB   65536
__device__ float g_ckpt[(NCHUNK - 1) * MAXB * 3];

template <int N> struct Prop {
    float pu[N], m00[N], m01[N], m10[N], m11[N], c0[N], c1[N];
};

template <int N>
__device__ __forceinline__ void make_prop(float h, const float* Om, const float* g,
                                          Prop<N>& P)
{
    const float i6 = 1.f / 6.f, i24 = 1.f / 24.f;
#pragma unroll
    for (int j = 0; j < N; ++j) {
        float b00 = -g[j] * h, b01 = -Om[j] * h, b10 = Om[j] * h, b11 = -2.f * g[j] * h;
        float s00 = b00 * b00 + b01 * b10;
        float s01 = b00 * b01 + b01 * b11;
        float s10 = b10 * b00 + b11 * b10;
        float s11 = b10 * b01 + b11 * b11;
        float t00 = s00 * b00 + s01 * b10;
        float t01 = s00 * b01 + s01 * b11;
        float t10 = s10 * b00 + s11 * b10;
        float t11 = s10 * b01 + s11 * b11;
        float q00 = s00 * s00 + s01 * s10;
        float q01 = s00 * s01 + s01 * s11;
        float q10 = s10 * s00 + s11 * s10;
        float q11 = s10 * s01 + s11 * s11;
        P.m00[j] = 1.f + b00 + 0.5f * s00 + i6 * t00 + i24 * q00;
        P.m01[j] =       b01 + 0.5f * s01 + i6 * t01 + i24 * q01;
        P.m10[j] =       b10 + 0.5f * s10 + i6 * t10 + i24 * q10;
        P.m11[j] = 1.f + b11 + 0.5f * s11 + i6 * t11 + i24 * q11;
        float p01 = h * (0.5f * b01 + i6 * s01 + i24 * t01);
        float p11 = h * (1.f + 0.5f * b11 + i6 * s11 + i24 * t11);
        float nb = -2.f * g[j];
        P.c0[j] = p01 * nb;
        P.c1[j] = p11 * nb;
        float be = -g[j] * h;
        P.pu[j] = 1.f + be * (1.f + be * (0.5f + be * (i6 + be * i24)));
    }
}

template <int N>
__device__ __forceinline__ void apply_prop(const Prop<N>& P, float* u, float* v, float* w)
{
#pragma unroll
    for (int j = 0; j < N; ++j) {
        u[j] = P.pu[j] * u[j];
        float vn = fmaf(P.m00[j], v[j], fmaf(P.m01[j], w[j], P.c0[j]));
        float wn = fmaf(P.m10[j], v[j], fmaf(P.m11[j], w[j], P.c1[j]));
        v[j] = vn; w[j] = wn;
    }
}

// 2-slot LRU propagator cache keyed on the fp32 dt value.
template <int N> struct PropCache {
    Prop<N> P0, P1;
    float h0, h1;
    bool last0;
    __device__ __forceinline__ void init() {
        h0 = __int_as_float(0x7fc00000);
        h1 = __int_as_float(0x7fc00000);
        last0 = false;
    }
    __device__ __forceinline__ void step(float h, const float* Om, const float* g,
                                         float* u, float* v, float* w) {
        if (h == h0)       { apply_prop(P0, u, v, w); last0 = true;  }
        else if (h == h1)  { apply_prop(P1, u, v, w); last0 = false; }
        else if (!last0)   { make_prop(h, Om, g, P0); h0 = h;
                             apply_prop(P0, u, v, w); last0 = true;  }
        else               { make_prop(h, Om, g, P1); h1 = h;
                             apply_prop(P1, u, v, w); last0 = false; }
    }
};

__device__ __forceinline__ void build_h(const float* __restrict__ ts, float* s_h, int T)
{
    for (int i = threadIdx.x + 1; i < T; i += blockDim.x)
        s_h[i] = ts[i] - ts[i - 1];
    __syncthreads();
}

// ---------------- Kernel 1: checkpoint states only (2 elems/thread) --------
__global__ __launch_bounds__(256) void bloch_ckpt_kernel(
    const float* __restrict__ y0,
    const float* __restrict__ ts,
    const float* __restrict__ params,
    int B, int T, int L)
{
    __shared__ float s_h[TMAX];
    build_h(ts, s_h, T);

    int tid = blockIdx.x * blockDim.x + threadIdx.x;
    long long e = 2LL * tid;            // first of 2 elements
    if (e >= B) return;

    float u[2], v[2], w[2], Om[2], g[2];
    u[0] = y0[3 * e + 0]; v[0] = y0[3 * e + 1]; w[0] = y0[3 * e + 2];
    u[1] = y0[3 * e + 3]; v[1] = y0[3 * e + 4]; w[1] = y0[3 * e + 5];
    Om[0] = params[3 * e + 0]; g[0] = params[3 * e + 2];
    Om[1] = params[3 * e + 3]; g[1] = params[3 * e + 5];

    PropCache<2> C;
    C.init();

    int s_end = (NCHUNK - 1) * L;
    if (s_end > T - 1) s_end = T - 1;

    int next_c = 1;
    for (int s = 1; s <= s_end; ++s) {
        C.step(s_h[s], Om, g, u, v, w);
        if (s == next_c * L) {
            float2* o = (float2*)(g_ckpt + (long long)(next_c - 1) * B * 3 + e * 3);
            __stcg(o + 0, make_float2(u[0], v[0]));
            __stcg(o + 1, make_float2(w[0], u[1]));
            __stcg(o + 2, make_float2(v[1], w[1]));
            ++next_c;
        }
    }
}

// ------- Kernel 2: output pass, one float4 per thread per step -------------
// float4 f covers floats [4f,4f+4) = components of elements e,e+1 with
// e = (4f)/3, off = 4f-3e. Thread simulates both elements (redundant 1.5x).
__global__ __launch_bounds__(128) void bloch_out_kernel(
    const float* __restrict__ y0,
    const float* __restrict__ ts,
    const float* __restrict__ params,
    float* __restrict__ out,
    int B, int T, int L)
{
    __shared__ float s_h[TMAX];
    build_h(ts, s_h, T);

    int c = blockIdx.y;
    int f = blockIdx.x * blockDim.x + threadIdx.x;
    int F = (3 * B) / 4;                 // float4s per timestep row
    if (f >= F) return;

    int sc = 1 + c * L;                  // first step of this chunk
    if (sc >= T) return;
    int se = sc + L;
    if (se > T) se = T;

    int e   = (4 * f) / 3;
    int off = 4 * f - 3 * e;
    bool o1 = (off >= 1), o2 = (off == 2);

    const float* src = (c == 0) ? y0 : (g_ckpt + (long long)(c - 1) * B * 3);
    float u[2], v[2], w[2], Om[2], g[2];
    u[0] = src[3 * e + 0]; v[0] = src[3 * e + 1]; w[0] = src[3 * e + 2];
    u[1] = src[3 * e + 3]; v[1] = src[3 * e + 4]; w[1] = src[3 * e + 5];
    Om[0] = params[3 * e + 0]; g[0] = params[3 * e + 2];
    Om[1] = params[3 * e + 3]; g[1] = params[3 * e + 5];

    float4* orow = (float4*)out + (long long)(sc - 1) * F + f;

#define STORE_ROW()                                                          \
    do {                                                                     \
        float x0 = o1 ? (o2 ? w[0] : v[0]) : u[0];                           \
        float x1 = o1 ? (o2 ? u[1] : w[0]) : v[0];                           \
        float x2 = o1 ? (o2 ? v[1] : u[1]) : w[0];                           \
        float x3 = o1 ? (o2 ? w[1] : v[1]) : u[1];                           \
        __stcs(orow, make_float4(x0, x1, x2, x3));                           \
    } while (0)

    if (c == 0) STORE_ROW();

    PropCache<2> C;
    C.init();

    if (se - sc == 32) {
        // fast path: compile-time trip count -> unrolled, LDS batched
#pragma unroll 4
        for (int k = 0; k < 32; ++k) {
            C.step(s_h[sc + k], Om, g, u, v, w);
            orow += F;
            STORE_ROW();
        }
    } else {
        for (int s = sc; s < se; ++s) {
            C.step(s_h[s], Om, g, u, v, w);
            orow += F;
            STORE_ROW();
        }
    }
#undef STORE_ROW
}

// ---------------- scalar fallback (any B, any T) ---------------------------
__global__ __launch_bounds__(256) void bloch_rk4_scalar(
    const float* __restrict__ y0,
    const float* __restrict__ ts,
    const float* __restrict__ params,
    float* __restrict__ out,
    int B, int T)
{
    int b = blockIdx.x * blockDim.x + threadIdx.x;
    if (b >= B) return;

    float u[1] = {y0[3 * b + 0]}, v[1] = {y0[3 * b + 1]}, w[1] = {y0[3 * b + 2]};
    float Om[1] = {params[3 * b + 0]}, g[1] = {params[3 * b + 2]};

    const long long B3 = 3LL * B;
    float* o = out + 3LL * b;
    o[0] = u[0]; o[1] = v[0]; o[2] = w[0];

    PropCache<1> C;
    C.init();
    float ts_prev = ts[0];

    for (int t = 1; t < T; ++t) {
        float ts_cur = __ldg(ts + t);
        float h = ts_cur - ts_prev;
        ts_prev = ts_cur;
        C.step(h, Om, g, u, v, w);
        o += B3;
        o[0] = u[0]; o[1] = v[0]; o[2] = w[0];
    }
}

extern "C" void kernel_launch(void* const* d_in, const int* in_sizes, int n_in,
                              void* d_out, int out_size) {
    const float* y0     = (const float*)d_in[0];   // (B,3)
    const float* ts     = (const float*)d_in[1];   // (T,)
    const float* params = (const float*)d_in[2];   // (B,3)
    float* out = (float*)d_out;                    // (T,B,3)

    int B = in_sizes[0] / 3;
    int T = in_sizes[1];

    if ((B & 3) == 0 && B <= MAXB && T >= 2 && T <= TMAX) {
        int L = (T - 1 + NCHUNK - 1) / NCHUNK;     // steps per chunk

        int n1 = (B + 1) / 2;
        int tpb1 = 256;
        bloch_ckpt_kernel<<<(n1 + tpb1 - 1) / tpb1, tpb1>>>(y0, ts, params, B, T, L);

        int F = (3 * B) / 4;
        int tpb2 = 128;
        dim3 grid2((F + tpb2 - 1) / tpb2, NCHUNK);
        bloch_out_kernel<<<grid2, tpb2>>>(y0, ts, params, out, B, T, L);
    } else {
        int tpb = 256;
        bloch_rk4_scalar<<<(B + tpb - 1) / tpb, tpb>>>(y0, ts, params, out, B, T);
    }
}

// round 7
// speedup vs baseline: 1.8164x; 1.0907x over previous
#include <cuda_runtime.h>
#include <cuda_bf16.h>

// Batched Bloch RK4. RHS is affine per batch element:
//   u' = -g u ;  [v w]' = [[-g,-Om],[Om,-2g]][v w] + [0,-2g]
// RK4 with step h on y'=Ay+b is EXACTLY y+ = M y + c (degree-4 Taylor).
//
// Two-phase time-split:
//   kernel1: sequential recurrence, 1 elem/thread, chunked + unrolled-8
//            inner loop (batched LDS, hidden pred chain); stores NCHUNK-1
//            checkpoint states only.
//   kernel2: NCHUNK time-chunks in parallel; each THREAD owns one output
//            float4 per step (spans 2 batch elements, simulated redundantly)
//            -> lane-contiguous STG.128. Memory-bound at ~6 TB/s.

#ifndef TMAX
#define TMAX 2048
#endif

#define NCHUNK 16
#define MAXB   65536
__device__ float g_ckpt[(NCHUNK - 1) * MAXB * 3];

template <int N> struct Prop {
    float pu[N], m00[N], m01[N], m10[N], m11[N], c0[N], c1[N];
};

template <int N>
__device__ __forceinline__ void make_prop(float h, const float* Om, const float* g,
                                          Prop<N>& P)
{
    const float i6 = 1.f / 6.f, i24 = 1.f / 24.f;
#pragma unroll
    for (int j = 0; j < N; ++j) {
        float b00 = -g[j] * h, b01 = -Om[j] * h, b10 = Om[j] * h, b11 = -2.f * g[j] * h;
        float s00 = b00 * b00 + b01 * b10;
        float s01 = b00 * b01 + b01 * b11;
        float s10 = b10 * b00 + b11 * b10;
        float s11 = b10 * b01 + b11 * b11;
        float t00 = s00 * b00 + s01 * b10;
        float t01 = s00 * b01 + s01 * b11;
        float t10 = s10 * b00 + s11 * b10;
        float t11 = s10 * b01 + s11 * b11;
        float q00 = s00 * s00 + s01 * s10;
        float q01 = s00 * s01 + s01 * s11;
        float q10 = s10 * s00 + s11 * s10;
        float q11 = s10 * s01 + s11 * s11;
        P.m00[j] = 1.f + b00 + 0.5f * s00 + i6 * t00 + i24 * q00;
        P.m01[j] =       b01 + 0.5f * s01 + i6 * t01 + i24 * q01;
        P.m10[j] =       b10 + 0.5f * s10 + i6 * t10 + i24 * q10;
        P.m11[j] = 1.f + b11 + 0.5f * s11 + i6 * t11 + i24 * q11;
        float p01 = h * (0.5f * b01 + i6 * s01 + i24 * t01);
        float p11 = h * (1.f + 0.5f * b11 + i6 * s11 + i24 * t11);
        float nb = -2.f * g[j];
        P.c0[j] = p01 * nb;
        P.c1[j] = p11 * nb;
        float be = -g[j] * h;
        P.pu[j] = 1.f + be * (1.f + be * (0.5f + be * (i6 + be * i24)));
    }
}

template <int N>
__device__ __forceinline__ void apply_prop(const Prop<N>& P, float* u, float* v, float* w)
{
#pragma unroll
    for (int j = 0; j < N; ++j) {
        u[j] = P.pu[j] * u[j];
        float vn = fmaf(P.m00[j], v[j], fmaf(P.m01[j], w[j], P.c0[j]));
        float wn = fmaf(P.m10[j], v[j], fmaf(P.m11[j], w[j], P.c1[j]));
        v[j] = vn; w[j] = wn;
    }
}

// 2-slot LRU propagator cache keyed on the fp32 dt value.
template <int N> struct PropCache {
    Prop<N> P0, P1;
    float h0, h1;
    bool last0;
    __device__ __forceinline__ void init() {
        h0 = __int_as_float(0x7fc00000);
        h1 = __int_as_float(0x7fc00000);
        last0 = false;
    }
    __device__ __forceinline__ void step(float h, const float* Om, const float* g,
                                         float* u, float* v, float* w) {
        if (h == h0)       { apply_prop(P0, u, v, w); last0 = true;  }
        else if (h == h1)  { apply_prop(P1, u, v, w); last0 = false; }
        else if (!last0)   { make_prop(h, Om, g, P0); h0 = h;
                             apply_prop(P0, u, v, w); last0 = true;  }
        else               { make_prop(h, Om, g, P1); h1 = h;
                             apply_prop(P1, u, v, w); last0 = false; }
    }
};

__device__ __forceinline__ void build_h(const float* __restrict__ ts, float* s_h, int T)
{
    for (int i = threadIdx.x + 1; i < T; i += blockDim.x)
        s_h[i] = ts[i] - ts[i - 1];
    __syncthreads();
}

// ---------------- Kernel 1: checkpoint states only (1 elem/thread) ---------
__global__ __launch_bounds__(128) void bloch_ckpt_kernel(
    const float* __restrict__ y0,
    const float* __restrict__ ts,
    const float* __restrict__ params,
    int B, int T, int L)
{
    __shared__ float s_h[TMAX];
    build_h(ts, s_h, T);

    int e = blockIdx.x * blockDim.x + threadIdx.x;
    if (e >= B) return;

    float u[1] = {y0[3 * e + 0]}, v[1] = {y0[3 * e + 1]}, w[1] = {y0[3 * e + 2]};
    float Om[1] = {params[3 * e + 0]}, g[1] = {params[3 * e + 2]};

    PropCache<1> C;
    C.init();

    for (int c = 1; c < NCHUNK; ++c) {
        int s0 = (c - 1) * L + 1;          // first step of this chunk
        if (s0 >= T) break;
        int s1 = c * L;                    // last step (checkpoint position)
        if (s1 > T - 1) s1 = T - 1;

        if (s1 - s0 + 1 == 32) {
            // fast path: fixed trip -> unrolled, LDS batched, preds overlap
#pragma unroll 8
            for (int k = 0; k < 32; ++k)
                C.step(s_h[s0 + k], Om, g, u, v, w);
        } else {
            for (int s = s0; s <= s1; ++s)
                C.step(s_h[s], Om, g, u, v, w);
        }

        float* o = g_ckpt + (long long)(c - 1) * B * 3 + 3LL * e;
        __stcg(o + 0, u[0]);
        __stcg(o + 1, v[0]);
        __stcg(o + 2, w[0]);
    }
}

// ------- Kernel 2: output pass, one float4 per thread per step -------------
// float4 f covers floats [4f,4f+4) = components of elements e,e+1 with
// e = (4f)/3, off = 4f-3e. Thread simulates both elements (redundant 1.5x).
__global__ __launch_bounds__(128) void bloch_out_kernel(
    const float* __restrict__ y0,
    const float* __restrict__ ts,
    const float* __restrict__ params,
    float* __restrict__ out,
    int B, int T, int L)
{
    __shared__ float s_h[TMAX];
    build_h(ts, s_h, T);

    int c = blockIdx.y;
    int f = blockIdx.x * blockDim.x + threadIdx.x;
    int F = (3 * B) / 4;                 // float4s per timestep row
    if (f >= F) return;

    int sc = 1 + c * L;                  // first step of this chunk
    if (sc >= T) return;
    int se = sc + L;
    if (se > T) se = T;

    int e   = (4 * f) / 3;
    int off = 4 * f - 3 * e;
    bool o1 = (off >= 1), o2 = (off == 2);

    const float* src = (c == 0) ? y0 : (g_ckpt + (long long)(c - 1) * B * 3);
    float u[2], v[2], w[2], Om[2], g[2];
    u[0] = src[3 * e + 0]; v[0] = src[3 * e + 1]; w[0] = src[3 * e + 2];
    u[1] = src[3 * e + 3]; v[1] = src[3 * e + 4]; w[1] = src[3 * e + 5];
    Om[0] = params[3 * e + 0]; g[0] = params[3 * e + 2];
    Om[1] = params[3 * e + 3]; g[1] = params[3 * e + 5];

    float4* orow = (float4*)out + (long long)(sc - 1) * F + f;

#define STORE_ROW()                                                          \
    do {                                                                     \
        float x0 = o1 ? (o2 ? w[0] : v[0]) : u[0];                           \
        float x1 = o1 ? (o2 ? u[1] : w[0]) : v[0];                           \
        float x2 = o1 ? (o2 ? v[1] : u[1]) : w[0];                           \
        float x3 = o1 ? (o2 ? w[1] : v[1]) : u[1];                           \
        __stcs(orow, make_float4(x0, x1, x2, x3));                           \
    } while (0)

    if (c == 0) STORE_ROW();

    PropCache<2> C;
    C.init();

    if (se - sc == 32) {
#pragma unroll 4
        for (int k = 0; k < 32; ++k) {
            C.step(s_h[sc + k], Om, g, u, v, w);
            orow += F;
            STORE_ROW();
        }
    } else {
        for (int s = sc; s < se; ++s) {
            C.step(s_h[s], Om, g, u, v, w);
            orow += F;
            STORE_ROW();
        }
    }
#undef STORE_ROW
}

// ---------------- scalar fallback (any B, any T) ---------------------------
__global__ __launch_bounds__(256) void bloch_rk4_scalar(
    const float* __restrict__ y0,
    const float* __restrict__ ts,
    const float* __restrict__ params,
    float* __restrict__ out,
    int B, int T)
{
    int b = blockIdx.x * blockDim.x + threadIdx.x;
    if (b >= B) return;

    float u[1] = {y0[3 * b + 0]}, v[1] = {y0[3 * b + 1]}, w[1] = {y0[3 * b + 2]};
    float Om[1] = {params[3 * b + 0]}, g[1] = {params[3 * b + 2]};

    const long long B3 = 3LL * B;
    float* o = out + 3LL * b;
    o[0] = u[0]; o[1] = v[0]; o[2] = w[0];

    PropCache<1> C;
    C.init();
    float ts_prev = ts[0];

    for (int t = 1; t < T; ++t) {
        float ts_cur = __ldg(ts + t);
        float h = ts_cur - ts_prev;
        ts_prev = ts_cur;
        C.step(h, Om, g, u, v, w);
        o += B3;
        o[0] = u[0]; o[1] = v[0]; o[2] = w[0];
    }
}

extern "C" void kernel_launch(void* const* d_in, const int* in_sizes, int n_in,
                              void* d_out, int out_size) {
    const float* y0     = (const float*)d_in[0];   // (B,3)
    const float* ts     = (const float*)d_in[1];   // (T,)
    const float* params = (const float*)d_in[2];   // (B,3)
    float* out = (float*)d_out;                    // (T,B,3)

    int B = in_sizes[0] / 3;
    int T = in_sizes[1];

    if ((B & 3) == 0 && B <= MAXB && T >= 2 && T <= TMAX) {
        int L = (T - 1 + NCHUNK - 1) / NCHUNK;     // steps per chunk

        int tpb1 = 128;
        bloch_ckpt_kernel<<<(B + tpb1 - 1) / tpb1, tpb1>>>(y0, ts, params, B, T, L);

        int F = (3 * B) / 4;
        int tpb2 = 128;
        dim3 grid2((F + tpb2 - 1) / tpb2, NCHUNK);
        bloch_out_kernel<<<grid2, tpb2>>>(y0, ts, params, out, B, T, L);
    } else {
        int tpb = 256;
        bloch_rk4_scalar<<<(B + tpb - 1) / tpb, tpb>>>(y0, ts, params, out, B, T);
    }
}